// round 8
// baseline (speedup 1.0000x reference)
#include <cuda_runtime.h>
#include <cuda_bf16.h>
#include <math.h>
#include <stdint.h>

#define BATCH   64
#define CH      96
#define HW      12544
#define MTOK    6
#define HEADS   4
#define RQ      24
#define DMODEL  192
#define QDIM    384
// SCALE * log2(e): scores feed ex2 directly
#define SCALE_F (0.10206207261596575f * 1.4426950408889634f)
#define SPLITS  14
#define CHUNK   896
#define TILE    64
#define TILES_PER 14        // CHUNK / TILE
#define KQ      8           // qproj split-k
#define FSTR    68          // fp32 per staging row (64+4)
#define XSTR    72          // bf16 per X row (64+8)
#define QSTR    104         // bf16 per Q row (96+8)
#define PSTR    72

#define OFF_XF0  0
#define OFF_XF1  26112      // 96*68*4
#define OFF_Q    52224
#define OFF_X    58880      // + 32*104*2
#define OFF_P    72704      // + 96*72*2
#define OFF_LR   77312      // + 32*72*2
#define SMEM_TOT 78848

__device__ float g_Qp[KQ * BATCH * RQ * CH];
__device__ float g_Lx[BATCH * SPLITS * RQ];
__device__ float g_Ox[BATCH * SPLITS * RQ * CH];

// ---------------------------------------------------------------------------
__device__ __forceinline__ uint32_t smem_u32(const void* p) {
    return (uint32_t)__cvta_generic_to_shared(p);
}
__device__ __forceinline__ void ldm_x4(uint32_t& r0, uint32_t& r1, uint32_t& r2,
                                       uint32_t& r3, uint32_t addr) {
    asm volatile("ldmatrix.sync.aligned.m8n8.x4.shared.b16 {%0,%1,%2,%3}, [%4];"
                 : "=r"(r0), "=r"(r1), "=r"(r2), "=r"(r3) : "r"(addr));
}
__device__ __forceinline__ void ldm_x2(uint32_t& r0, uint32_t& r1, uint32_t addr) {
    asm volatile("ldmatrix.sync.aligned.m8n8.x2.shared.b16 {%0,%1}, [%2];"
                 : "=r"(r0), "=r"(r1) : "r"(addr));
}
__device__ __forceinline__ void ldm_x2_t(uint32_t& r0, uint32_t& r1, uint32_t addr) {
    asm volatile("ldmatrix.sync.aligned.m8n8.x2.trans.shared.b16 {%0,%1}, [%2];"
                 : "=r"(r0), "=r"(r1) : "r"(addr));
}
__device__ __forceinline__ void mma16816(float* c, const uint32_t* a,
                                         uint32_t b0, uint32_t b1) {
    asm volatile("mma.sync.aligned.m16n8k16.row.col.f32.bf16.bf16.f32 "
                 "{%0,%1,%2,%3}, {%4,%5,%6,%7}, {%8,%9}, {%0,%1,%2,%3};"
                 : "+f"(c[0]), "+f"(c[1]), "+f"(c[2]), "+f"(c[3])
                 : "r"(a[0]), "r"(a[1]), "r"(a[2]), "r"(a[3]), "r"(b0), "r"(b1));
}
__device__ __forceinline__ void cpasync16(uint32_t dst, const void* src) {
    asm volatile("cp.async.cg.shared.global [%0], [%1], 16;" :: "r"(dst), "l"(src));
}
#define CP_COMMIT() asm volatile("cp.async.commit_group;" ::: "memory")
#define CP_WAIT0()  asm volatile("cp.async.wait_group 0;" ::: "memory")
#define CP_WAIT1()  asm volatile("cp.async.wait_group 1;" ::: "memory")

__device__ __forceinline__ uint32_t pack_bf16(float a, float b) {
    __nv_bfloat162 h2 = __floats2bfloat162_rn(a, b);
    return *(uint32_t*)&h2;
}
__device__ __forceinline__ float ex2(float x) {
    float r;
    asm("ex2.approx.f32 %0, %1;" : "=f"(r) : "f"(x));
    return r;
}

// ---------------------------------------------------------------------------
// Kernel 1: Q projection, split-k x8. grid (BATCH, KQ), 384 threads.
// ---------------------------------------------------------------------------
__global__ __launch_bounds__(QDIM) void qproj_kernel(
    const float* __restrict__ z, const float* __restrict__ Wq,
    const float* __restrict__ bq)
{
    __shared__ float sz[MTOK * 24];
    const int b = blockIdx.x, kq = blockIdx.y, col = threadIdx.x;
    if (col < MTOK * 24) {
        const int m = col / 24, k = col - m * 24;
        sz[col] = z[b * MTOK * DMODEL + m * DMODEL + kq * 24 + k];
    }
    __syncthreads();

    float acc[MTOK];
    const float b0 = (kq == 0) ? bq[col] : 0.f;
    #pragma unroll
    for (int m = 0; m < MTOK; ++m) acc[m] = b0;

    const float* Wqp = Wq + (size_t)(kq * 24) * QDIM + col;
    #pragma unroll
    for (int k = 0; k < 24; ++k) {
        const float w = __ldg(Wqp + k * QDIM);
        #pragma unroll
        for (int m = 0; m < MTOK; ++m)
            acc[m] = fmaf(sz[m * 24 + k], w, acc[m]);
    }
    const int h = col / CH, c = col - h * CH;
    #pragma unroll
    for (int m = 0; m < MTOK; ++m)
        g_Qp[kq * (BATCH * RQ * CH) + (b * RQ + h * MTOK + m) * CH + c] = acc[m] * SCALE_F;
}

// ---------------------------------------------------------------------------
// Kernel 2: fixed-max flash attention; TILE=64, double-buffered fp32 staging;
// prefetch(t+1) issued before the wait for t => continuous DRAM pipeline.
// 8 warps, occ 2. Warp owns 8 spatial cols for QK/exp; PV as in R7.
// ---------------------------------------------------------------------------
__global__ __launch_bounds__(256, 2) void attn_partial_kernel(const float* __restrict__ x)
{
    extern __shared__ char smem[];
    float*         sXf0 = (float*)(smem + OFF_XF0);
    float*         sXf1 = (float*)(smem + OFF_XF1);
    __nv_bfloat16* sQ   = (__nv_bfloat16*)(smem + OFF_Q);
    __nv_bfloat16* sX   = (__nv_bfloat16*)(smem + OFF_X);
    __nv_bfloat16* sP   = (__nv_bfloat16*)(smem + OFF_P);
    float*         sLr  = (float*)(smem + OFF_LR);

    const int b = blockIdx.y, s = blockIdx.x;
    const int tid = threadIdx.x, lane = tid & 31, warp = tid >> 5;
    const int g = lane >> 2, tig = lane & 3;
    const int grp = lane >> 3;

    const uint32_t uQ   = smem_u32(sQ);
    const uint32_t uX   = smem_u32(sX);
    const uint32_t uP   = smem_u32(sP);
    const uint32_t uXf0 = smem_u32(sXf0);
    const uint32_t uXf1 = smem_u32(sXf1);

    const float* xb = x + (size_t)b * CH * HW + (size_t)s * CHUNK;

    // ---- prefetch tile 0 into buffer 0 ----
    #pragma unroll
    for (int r = 0; r < 6; ++r) {
        const int i = tid + 256 * r;
        const int c = i >> 4, n4 = (i & 15) << 2;   // 16 float4 per 64-col row
        cpasync16(uXf0 + (c * FSTR + n4) * 4, xb + (size_t)c * HW + n4);
    }
    CP_COMMIT();

    // ---- stage Q (sum KQ split-k partials -> bf16), rows 24..31 zero ----
    for (int i = tid; i < 32 * CH; i += 256) {
        const int r = i / CH, c = i - r * CH;
        float v = 0.f;
        if (r < RQ) {
            const int idx = (b * RQ + r) * CH + c;
            #pragma unroll
            for (int k = 0; k < KQ; ++k) v += g_Qp[k * (BATCH * RQ * CH) + idx];
        }
        sQ[r * QSTR + c] = __float2bfloat16(v);
    }
    __syncthreads();

    // ---- hoist Q A-fragments ----
    uint32_t qf[2][6][4];
    #pragma unroll
    for (int i = 0; i < 6; ++i) {
        ldm_x4(qf[0][i][0], qf[0][i][1], qf[0][i][2], qf[0][i][3],
               uQ + (((lane & 15)     ) * QSTR + i * 16 + (lane >> 4) * 8) * 2);
        ldm_x4(qf[1][i][0], qf[1][i][1], qf[1][i][2], qf[1][i][3],
               uQ + ((16 + (lane & 15)) * QSTR + i * 16 + (lane >> 4) * 8) * 2);
    }

    float runL[4] = {0.f, 0.f, 0.f, 0.f};
    float oacc[12];
    #pragma unroll
    for (int j = 0; j < 12; ++j) oacc[j] = 0.f;

    const int mt_o  = warp & 1;
    const int cbase = 24 * (warp >> 1);
    const int cw    = 8 * warp;                  // own 8 spatial cols

    for (int t = 0; t < TILES_PER; ++t) {
        // ---- issue prefetch t+1 into the other buffer, then wait for t ----
        if (t + 1 < TILES_PER) {
            const uint32_t uDst = ((t + 1) & 1) ? uXf1 : uXf0;
            const float* xt = xb + (t + 1) * TILE;
            #pragma unroll
            for (int r = 0; r < 6; ++r) {
                const int i = tid + 256 * r;
                const int c = i >> 4, n4 = (i & 15) << 2;
                cpasync16(uDst + (c * FSTR + n4) * 4, xt + (size_t)c * HW + n4);
            }
            CP_COMMIT();
            CP_WAIT1();    // group t complete; group t+1 still in flight
        } else {
            CP_WAIT0();
        }
        __syncthreads();   // tile t staged; PV(t-1) fully done with sX/sP

        const float* sXf = (t & 1) ? sXf1 : sXf0;

        // ---- convert OWN 8 cols fp32 -> bf16 (conflict-free: rows 0..31/pass) ----
        #pragma unroll
        for (int p = 0; p < 6; ++p) {
            const int row = lane + 32 * (p >> 1);
            const int co  = cw + 4 * (p & 1);
            float4 v = *reinterpret_cast<const float4*>(&sXf[row * FSTR + co]);
            uint2 pk2;
            pk2.x = pack_bf16(v.x, v.y);
            pk2.y = pack_bf16(v.z, v.w);
            *reinterpret_cast<uint2*>(&sX[row * XSTR + co]) = pk2;
        }
        __syncwarp();

        // ---- QK on own 8 cols ----
        float sc[2][4];
        #pragma unroll
        for (int mt = 0; mt < 2; ++mt)
            #pragma unroll
            for (int e = 0; e < 4; ++e) sc[mt][e] = 0.f;

        #pragma unroll
        for (int i = 0; i < 6; ++i) {
            uint32_t b0, b1;
            const int row = i * 16 + (lane & 15);
            ldm_x2_t(b0, b1, uX + (row * XSTR + cw) * 2);
            mma16816(sc[0], qf[0][i], b0, b1);
            mma16816(sc[1], qf[1][i], b0, b1);
        }

        // ---- P = 2^score, private L, P -> smem ----
        #pragma unroll
        for (int mt = 0; mt < 2; ++mt)
            #pragma unroll
            for (int hl = 0; hl < 2; ++hl) {
                float p0 = ex2(sc[mt][hl*2]);
                float p1 = ex2(sc[mt][hl*2+1]);
                runL[mt*2 + hl] += p0 + p1;
                const int row = 16*mt + g + 8*hl;
                *reinterpret_cast<__nv_bfloat162*>(&sP[row * PSTR + cw + 2*tig]) =
                    __floats2bfloat162_rn(p0, p1);
            }
        __syncthreads();   // full sX + sP visible to all warps

        // ---- PV: m-tile mt_o, channels [cbase, cbase+24), k = 64 spatial ----
        #pragma unroll
        for (int i = 0; i < 4; ++i) {
            uint32_t a[4], b01[4], b2[2];
            ldm_x4(a[0], a[1], a[2], a[3],
                   uP + ((16*mt_o + (lane & 15)) * PSTR + i * 16 + (lane >> 4) * 8) * 2);
            {
                const int row = cbase + (grp >> 1) * 8 + (lane & 7);
                const int col = i * 16 + (grp & 1) * 8;
                ldm_x4(b01[0], b01[1], b01[2], b01[3], uX + (row * XSTR + col) * 2);
            }
            {
                const int row = cbase + 16 + (lane & 7);
                const int col = i * 16 + ((lane >> 3) & 1) * 8;
                ldm_x2(b2[0], b2[1], uX + (row * XSTR + col) * 2);
            }
            mma16816(oacc + 0, a, b01[0], b01[1]);
            mma16816(oacc + 4, a, b01[2], b01[3]);
            mma16816(oacc + 8, a, b2[0],  b2[1]);
        }
    }

    // ---- epilogue ----
    const int base = (b * SPLITS + s) * RQ;
    {
        const int r0 = 16*mt_o + g;
        #pragma unroll
        for (int j = 0; j < 3; ++j) {
            const int c0 = cbase + 8*j + 2*tig;
            g_Ox[(base + r0) * CH + c0]     = oacc[4*j+0];
            g_Ox[(base + r0) * CH + c0 + 1] = oacc[4*j+1];
        }
        if (mt_o == 0) {
            const int r1 = g + 8;
            #pragma unroll
            for (int j = 0; j < 3; ++j) {
                const int c0 = cbase + 8*j + 2*tig;
                g_Ox[(base + r1) * CH + c0]     = oacc[4*j+2];
                g_Ox[(base + r1) * CH + c0 + 1] = oacc[4*j+3];
            }
        }
    }
    #pragma unroll
    for (int j = 0; j < 4; ++j) {
        runL[j] += __shfl_xor_sync(0xffffffffu, runL[j], 1);
        runL[j] += __shfl_xor_sync(0xffffffffu, runL[j], 2);
    }
    if (tig == 0) {
        sLr[warp * 32 + g]      = runL[0];
        sLr[warp * 32 + g + 8]  = runL[1];
        sLr[warp * 32 + g + 16] = runL[2];
        sLr[warp * 32 + g + 24] = runL[3];
    }
    __syncthreads();
    if (tid < RQ) {
        float L = 0.f;
        #pragma unroll
        for (int w = 0; w < 8; ++w) L += sLr[w * 32 + tid];
        g_Lx[base + tid] = L;
    }
}

// ---------------------------------------------------------------------------
// Kernel 3: combine split partials + output projection + residual.
// ---------------------------------------------------------------------------
__global__ __launch_bounds__(DMODEL) void combine_proj_kernel(
    const float* __restrict__ z, const float* __restrict__ Wo,
    const float* __restrict__ bo, float* __restrict__ out)
{
    __shared__ float sOf[RQ * CH];
    __shared__ float sLi[RQ];
    const int b = blockIdx.x, tid = threadIdx.x;

    if (tid < RQ) {
        float L = 0.f;
        #pragma unroll
        for (int s = 0; s < SPLITS; ++s)
            L += g_Lx[(b * SPLITS + s) * RQ + tid];
        sLi[tid] = 1.f / L;
    }
    __syncthreads();

    for (int o = tid; o < RQ * CH; o += DMODEL) {
        const int q = o / CH, c = o - q * CH;
        float a = 0.f;
        #pragma unroll
        for (int s = 0; s < SPLITS; ++s)
            a += g_Ox[((b * SPLITS + s) * RQ + q) * CH + c];
        sOf[o] = a * sLi[q];
    }
    __syncthreads();

    float accv[MTOK];
    #pragma unroll
    for (int m = 0; m < MTOK; ++m)
        accv[m] = z[(b * MTOK + m) * DMODEL + tid] + bo[tid];

    for (int h = 0; h < HEADS; ++h) {
        #pragma unroll 4
        for (int c = 0; c < CH; ++c) {
            const float w = Wo[(h * CH + c) * DMODEL + tid];
            #pragma unroll
            for (int m = 0; m < MTOK; ++m)
                accv[m] = fmaf(sOf[(h * MTOK + m) * CH + c], w, accv[m]);
        }
    }
    #pragma unroll
    for (int m = 0; m < MTOK; ++m)
        out[(b * MTOK + m) * DMODEL + tid] = accv[m];
}

// ---------------------------------------------------------------------------
extern "C" void kernel_launch(void* const* d_in, const int* in_sizes, int n_in,
                              void* d_out, int out_size)
{
    const float* x  = (const float*)d_in[0];
    const float* z  = (const float*)d_in[1];
    const float* Wq = (const float*)d_in[2];
    const float* bq = (const float*)d_in[3];
    const float* Wo = (const float*)d_in[4];
    const float* bo = (const float*)d_in[5];
    float* out = (float*)d_out;

    cudaFuncSetAttribute(attn_partial_kernel,
                         cudaFuncAttributeMaxDynamicSharedMemorySize, SMEM_TOT);

    qproj_kernel<<<dim3(BATCH, KQ), QDIM>>>(z, Wq, bq);
    attn_partial_kernel<<<dim3(SPLITS, BATCH), 256, SMEM_TOT>>>(x);
    combine_proj_kernel<<<BATCH, DMODEL>>>(z, Wo, bo, out);
}